// round 15
// baseline (speedup 1.0000x reference)
#include <cuda_runtime.h>
#include <cuda.h>
#include <cuda_bf16.h>
#include <cstdint>

// ---------------------------------------------------------------------------
// Problem constants: B=4, S=2048, D=1024, H=16, hd=64, causal mask
// ---------------------------------------------------------------------------
#define BATCH 4
#define SEQ   2048
#define DMODEL 1024
#define NHEAD 16
#define HDIM  64
#define TD    (3 * DMODEL)          // 3072
#define MTOT  (BATCH * SEQ)         // 8192
#define NEG_BIG -1e30f
#define NSM_X2 304
#define EXSCALE (0.125f * 1.44269504f)   // 1/sqrt(64) * log2(e)

// Scratch (__device__ globals — allocation-free rule)
__device__ __nv_bfloat16 g_qkvhi[(size_t)MTOT * TD];
__device__ __nv_bfloat16 g_qkvlo[(size_t)MTOT * TD];
__device__ __nv_bfloat16 g_xhi[(size_t)MTOT * DMODEL];
__device__ __nv_bfloat16 g_xlo[(size_t)MTOT * DMODEL];
__device__ __nv_bfloat16 g_w1hi[(size_t)TD * DMODEL];
__device__ __nv_bfloat16 g_w1lo[(size_t)TD * DMODEL];
__device__ __nv_bfloat16 g_w2hi[(size_t)DMODEL * DMODEL];
__device__ __nv_bfloat16 g_w2lo[(size_t)DMODEL * DMODEL];
__device__ __nv_bfloat16 g_ohi[(size_t)MTOT * DMODEL];
__device__ __nv_bfloat16 g_olo[(size_t)MTOT * DMODEL];

// ---------------------------------------------------------------------------
// helpers
// ---------------------------------------------------------------------------
__device__ __forceinline__ void ldsm_x4(uint32_t* r, uint32_t addr) {
    asm volatile("ldmatrix.sync.aligned.m8n8.x4.shared.b16 {%0,%1,%2,%3}, [%4];"
                 : "=r"(r[0]), "=r"(r[1]), "=r"(r[2]), "=r"(r[3]) : "r"(addr));
}
__device__ __forceinline__ void ldsm_x4t(uint32_t* r, uint32_t addr) {
    asm volatile("ldmatrix.sync.aligned.m8n8.x4.trans.shared.b16 {%0,%1,%2,%3}, [%4];"
                 : "=r"(r[0]), "=r"(r[1]), "=r"(r[2]), "=r"(r[3]) : "r"(addr));
}
__device__ __forceinline__ void mma_bf16(float* d, const uint32_t* a, const uint32_t* b) {
    asm volatile("mma.sync.aligned.m16n8k16.row.col.f32.bf16.bf16.f32 "
                 "{%0,%1,%2,%3}, {%4,%5,%6,%7}, {%8,%9}, {%0,%1,%2,%3};"
                 : "+f"(d[0]), "+f"(d[1]), "+f"(d[2]), "+f"(d[3])
                 : "r"(a[0]), "r"(a[1]), "r"(a[2]), "r"(a[3]),
                   "r"(b[0]), "r"(b[1]));
}
__device__ __forceinline__ float ex2(float x) {
    float r;
    asm("ex2.approx.f32 %0, %1;" : "=f"(r) : "f"(x));
    return r;
}
__device__ __forceinline__ void packsplit(float v0, float v1, uint32_t& hi, uint32_t& lo) {
    __nv_bfloat162 hp = __float22bfloat162_rn(make_float2(v0, v1));
    hi = *reinterpret_cast<uint32_t*>(&hp);
    __nv_bfloat162 lp = __float22bfloat162_rn(make_float2(
        v0 - __bfloat162float(hp.x), v1 - __bfloat162float(hp.y)));
    lo = *reinterpret_cast<uint32_t*>(&lp);
}
// 64B rows (GEMM BK=32): matches CU_TENSOR_MAP_SWIZZLE_64B
__device__ __forceinline__ uint32_t swz(int row, int gran) {
    return (uint32_t)(row * 64 + ((gran ^ ((row >> 1) & 3)) << 4));
}
// 128B rows (attention hd=64): matches CU_TENSOR_MAP_SWIZZLE_128B
__device__ __forceinline__ uint32_t swz128(int row, int gran) {
    return (uint32_t)(row * 128 + ((gran ^ (row & 7)) << 4));
}
__device__ __forceinline__ void tma2d(uint32_t dst, const CUtensorMap* m,
                                      int cx, int cy, uint32_t mbar) {
    asm volatile(
        "cp.async.bulk.tensor.2d.shared::cta.global.tile.mbarrier::complete_tx::bytes "
        "[%0], [%1, {%2, %3}], [%4];"
        :: "r"(dst), "l"(m), "r"(cx), "r"(cy), "r"(mbar) : "memory");
}
__device__ __forceinline__ void mbar_init(uint32_t mbar, uint32_t cnt) {
    asm volatile("mbarrier.init.shared.b64 [%0], %1;" :: "r"(mbar), "r"(cnt) : "memory");
}
__device__ __forceinline__ void mbar_expect(uint32_t mbar, uint32_t bytes) {
    asm volatile("mbarrier.arrive.expect_tx.shared.b64 _, [%0], %1;"
                 :: "r"(mbar), "r"(bytes) : "memory");
}
__device__ __forceinline__ void mbar_arrive(uint32_t mbar) {
    asm volatile("mbarrier.arrive.shared.b64 _, [%0];" :: "r"(mbar) : "memory");
}
// acquire wait — consumer side (generic smem reads follow)
__device__ __forceinline__ void mbar_wait(uint32_t mbar, uint32_t parity) {
    uint32_t done;
    do {
        asm volatile(
            "{\n\t.reg .pred p;\n\t"
            "mbarrier.try_wait.parity.acquire.cta.shared::cta.b64 p, [%1], %2, 0x989680;\n\t"
            "selp.b32 %0, 1, 0, p;\n\t}"
            : "=r"(done) : "r"(mbar), "r"(parity) : "memory");
    } while (!done);
}
// relaxed wait — producer side ONLY (post-wait accesses are async-proxy TMA)
__device__ __forceinline__ void mbar_wait_rlx(uint32_t mbar, uint32_t parity) {
    uint32_t done;
    do {
        asm volatile(
            "{\n\t.reg .pred p;\n\t"
            "mbarrier.try_wait.parity.relaxed.cta.shared::cta.b64 p, [%1], %2, 0x989680;\n\t"
            "selp.b32 %0, 1, 0, p;\n\t}"
            : "=r"(done) : "r"(mbar), "r"(parity) : "memory");
    } while (!done);
}

// ---------------------------------------------------------------------------
// Fused prep: phase 0 split x, phase 1 transpose+split W_qkv, phase 2 W_out
// ---------------------------------------------------------------------------
#define SPLIT_BLKS (MTOT * DMODEL / 4 / 256)            // 8192
#define T1_BX (TD / 32)                                 // 96
#define T1_BLKS (T1_BX * (DMODEL / 32))                 // 3072
#define T2_BX (DMODEL / 32)                             // 32
#define T2_BLKS (T2_BX * (DMODEL / 32))                 // 1024
#define PREP_BLKS (SPLIT_BLKS + T1_BLKS + T2_BLKS)

__device__ __forceinline__ void do_transpose_split(
    const float* __restrict__ W, __nv_bfloat16* __restrict__ bhi,
    __nv_bfloat16* __restrict__ blo, int K, int N, int bidx, int bx_count)
{
    __shared__ float t[32][33];
    int nb = (bidx % bx_count) * 32, kb = (bidx / bx_count) * 32;
    int tx = threadIdx.x & 31, ty = threadIdx.x >> 5;
#pragma unroll
    for (int i = 0; i < 4; ++i)
        t[ty + i * 8][tx] = W[(size_t)(kb + ty + i * 8) * N + nb + tx];
    __syncthreads();
#pragma unroll
    for (int i = 0; i < 4; ++i) {
        int n = nb + ty + i * 8;
        int k = kb + tx;
        float v = t[tx][ty + i * 8];
        __nv_bfloat16 h = __float2bfloat16(v);
        bhi[(size_t)n * K + k] = h;
        blo[(size_t)n * K + k] = __float2bfloat16(v - __bfloat162float(h));
    }
}

__global__ __launch_bounds__(256) void prep_kernel(
    const float* __restrict__ x,
    __nv_bfloat16* __restrict__ xhi, __nv_bfloat16* __restrict__ xlo,
    const float* __restrict__ W1, __nv_bfloat16* __restrict__ w1hi,
    __nv_bfloat16* __restrict__ w1lo,
    const float* __restrict__ W2, __nv_bfloat16* __restrict__ w2hi,
    __nv_bfloat16* __restrict__ w2lo)
{
    int bid = blockIdx.x;
    if (bid < SPLIT_BLKS) {
        int i = bid * 256 + threadIdx.x;
        float4 v = ((const float4*)x)[i];
        uint32_t h0, l0, h1, l1;
        packsplit(v.x, v.y, h0, l0);
        packsplit(v.z, v.w, h1, l1);
        ((uint32_t*)xhi)[2*i] = h0; ((uint32_t*)xhi)[2*i+1] = h1;
        ((uint32_t*)xlo)[2*i] = l0; ((uint32_t*)xlo)[2*i+1] = l1;
    } else if (bid < SPLIT_BLKS + T1_BLKS) {
        do_transpose_split(W1, w1hi, w1lo, DMODEL, TD, bid - SPLIT_BLKS, T1_BX);
    } else {
        do_transpose_split(W2, w2hi, w2lo, DMODEL, DMODEL,
                           bid - SPLIT_BLKS - T1_BLKS, T2_BX);
    }
}

// ---------------------------------------------------------------------------
// bf16x3 HMMA GEMM: 128x128 tile, BK=32, 8 warps, TMA + full/empty mbarrier
// pipeline (3 stages), flat chunk stream across tiles, NO __syncthreads in
// the mainloop.  Producer duty distributed: chunk j issued by warp (j&7).
// ---------------------------------------------------------------------------
#define GSTAGE 32768
#define GSMEM (1024 + 3 * GSTAGE)       // 99328

__global__ __launch_bounds__(256, 2) void gemm_bf16x3(
    const __grid_constant__ CUtensorMap tAhi, const __grid_constant__ CUtensorMap tAlo,
    const __grid_constant__ CUtensorMap tBhi, const __grid_constant__ CUtensorMap tBlo,
    const float* __restrict__ bias, float* __restrict__ C,
    __nv_bfloat16* __restrict__ Chi, __nv_bfloat16* __restrict__ Clo,
    int bf16out, int M, int N, int K, int NTILES, int NBX)
{
    extern __shared__ char smraw[];
    char* smem = (char*)(((uintptr_t)smraw + 1023) & ~(uintptr_t)1023);
    const uint32_t sb = (uint32_t)__cvta_generic_to_shared(smem);
    const uint32_t tiles = sb + 1024;

    const int tid  = threadIdx.x;
    const int wid  = tid >> 5;
    const int lane = tid & 31;
    const int wm   = wid >> 2;
    const int wn   = wid & 3;
    const int NC = K >> 5;

    if (tid == 0) {
        mbar_init(sb + 0, 1);  mbar_init(sb + 8, 1);  mbar_init(sb + 16, 1);
        mbar_init(sb + 24, 8); mbar_init(sb + 32, 8); mbar_init(sb + 40, 8);
    }
    __syncthreads();

    int ntile = (NTILES - (int)blockIdx.x + (int)gridDim.x - 1) / (int)gridDim.x;
    if (ntile < 0) ntile = 0;
    const int total = ntile * NC;

    auto issue = [&](int j) {
        int tix = (int)blockIdx.x + (j / NC) * (int)gridDim.x;
        int kc = (j % NC) << 5;
        int im0 = (tix / NBX) * 128;
        int in0 = (tix % NBX) * 128;
        uint32_t s = (uint32_t)(j % 3);
        if (j >= 3) mbar_wait_rlx(sb + 24 + s * 8, (uint32_t)((j / 3 - 1) & 1));
        uint32_t stg = tiles + s * GSTAGE;
        uint32_t bar = sb + s * 8;
        mbar_expect(bar, 32768);
        tma2d(stg,         &tAhi, kc, im0, bar);
        tma2d(stg + 8192,  &tAlo, kc, im0, bar);
        tma2d(stg + 16384, &tBhi, kc, in0, bar);
        tma2d(stg + 24576, &tBlo, kc, in0, bar);
    };

    if (lane == 0) {
        if (wid == 0 && total > 0) issue(0);
        if (wid == 1 && total > 1) issue(1);
    }

    float acc[4][4][4];
    int jn = 0;
    int tix = (int)blockIdx.x;

    for (int j = 0; j < total; ++j) {
        const int m0 = (tix / NBX) * 128;
        const int n0 = (tix % NBX) * 128;

        if (jn == 0) {
#pragma unroll
            for (int i = 0; i < 4; ++i)
#pragma unroll
                for (int jj = 0; jj < 4; ++jj)
#pragma unroll
                    for (int c = 0; c < 4; ++c) acc[i][jj][c] = 0.0f;
        }

        if (lane == 0 && wid == ((j + 2) & 7) && j + 2 < total) issue(j + 2);

        const uint32_t s = (uint32_t)(j % 3);
        mbar_wait(sb + s * 8, (uint32_t)((j / 3) & 1));

        const uint32_t st = tiles + s * GSTAGE;
        const uint32_t sAhi = st, sAlo = st + 8192,
                       sBhi = st + 16384, sBlo = st + 24576;

#pragma unroll
        for (int kk = 0; kk < 2; ++kk) {
            uint32_t ah[4][4], al[4][4], bh[2][4], bl[2][4];
#pragma unroll
            for (int mi = 0; mi < 4; ++mi) {
                int row = wm * 64 + mi * 16 + (lane & 15);
                uint32_t off = swz(row, kk * 2 + (lane >> 4));
                ldsm_x4(ah[mi], sAhi + off);
                ldsm_x4(al[mi], sAlo + off);
            }
#pragma unroll
            for (int nj = 0; nj < 2; ++nj) {
                int row = wn * 32 + nj * 16 + (lane & 7) + ((lane >> 4) << 3);
                uint32_t off = swz(row, kk * 2 + ((lane >> 3) & 1));
                ldsm_x4(bh[nj], sBhi + off);
                ldsm_x4(bl[nj], sBlo + off);
            }
#pragma unroll
            for (int mi = 0; mi < 4; ++mi)
#pragma unroll
                for (int ni = 0; ni < 4; ++ni) {
                    const uint32_t* pbh = bh[ni >> 1] + (ni & 1) * 2;
                    const uint32_t* pbl = bl[ni >> 1] + (ni & 1) * 2;
                    mma_bf16(acc[mi][ni], ah[mi], pbh);
                    mma_bf16(acc[mi][ni], ah[mi], pbl);
                    mma_bf16(acc[mi][ni], al[mi], pbh);
                }
        }

        if (lane == 0) mbar_arrive(sb + 24 + s * 8);

        if (jn == NC - 1) {
            const int rbase = m0 + wm * 64 + (lane >> 2);
            const int cbase = n0 + wn * 32 + ((lane & 3) << 1);
#pragma unroll
            for (int mi = 0; mi < 4; ++mi)
#pragma unroll
                for (int ni = 0; ni < 4; ++ni) {
                    int r = rbase + mi * 16;
                    int c = cbase + ni * 8;
                    float b0 = bias[c], b1 = bias[c + 1];
                    float v0 = acc[mi][ni][0] + b0, v1 = acc[mi][ni][1] + b1;
                    float v2 = acc[mi][ni][2] + b0, v3 = acc[mi][ni][3] + b1;
                    if (!bf16out) {
                        *(float2*)(C + (size_t)r * N + c)       = make_float2(v0, v1);
                        *(float2*)(C + (size_t)(r + 8) * N + c) = make_float2(v2, v3);
                    } else {
                        float sc = ((c % 192) < 64) ? EXSCALE : 1.0f;
                        v0 *= sc; v1 *= sc; v2 *= sc; v3 *= sc;
                        uint32_t h, l;
                        packsplit(v0, v1, h, l);
                        *(uint32_t*)(Chi + (size_t)r * N + c) = h;
                        *(uint32_t*)(Clo + (size_t)r * N + c) = l;
                        packsplit(v2, v3, h, l);
                        *(uint32_t*)(Chi + (size_t)(r + 8) * N + c) = h;
                        *(uint32_t*)(Clo + (size_t)(r + 8) * N + c) = l;
                    }
                }
        }

        if (++jn == NC) { jn = 0; tix += (int)gridDim.x; }
    }
}

// ---------------------------------------------------------------------------
// Flash attention: persistent boustrophedon schedule, TMA + full/empty
// mbarrier pipeline, distributed KV producer, fine-grained causal skip.
// ---------------------------------------------------------------------------
#define AQOFF 1024
#define AKV   (1024 + 32768)
#define AKVST 32768
#define ASMEM (1024 + 32768 + 2 * 32768)   // 99328
#define NUNITS ((SEQ / 128) * NHEAD * BATCH)

__global__ __launch_bounds__(256, 2) void attn_flash_hmma(
    const __grid_constant__ CUtensorMap tQhi, const __grid_constant__ CUtensorMap tQlo,
    __nv_bfloat16* __restrict__ ohi, __nv_bfloat16* __restrict__ olo,
    const int* __restrict__ maskp)
{
    extern __shared__ char smraw[];
    char* smem = (char*)(((uintptr_t)smraw + 1023) & ~(uintptr_t)1023);
    const uint32_t sb = (uint32_t)__cvta_generic_to_shared(smem);

    const int tid  = threadIdx.x;
    const int wid  = tid >> 5;
    const int lane = tid & 31;
    const int use_mask = (maskp[0] != 0);
    const int G = (int)gridDim.x;

    if (tid == 0) {
        mbar_init(sb + 0, 1);    // Q full
        mbar_init(sb + 8, 1);    // KV full 0
        mbar_init(sb + 16, 1);   // KV full 1
        mbar_init(sb + 24, 8);   // Q empty
        mbar_init(sb + 32, 8);   // KV empty 0
        mbar_init(sb + 40, 8);   // KV empty 1
    }
    __syncthreads();

    uint32_t uc = 0;
    uint32_t icv = 0, ccv = 0;

    auto issue_kv = [&](int cx0, int cy, uint32_t j) {
        uint32_t s = j & 1;
        if (j >= 2) mbar_wait_rlx(sb + 32 + s * 8, ((j >> 1) - 1) & 1);
        uint32_t stg = sb + AKV + s * AKVST;
        uint32_t bar = sb + 8 + s * 8;
        mbar_expect(bar, 32768);
        tma2d(stg,         &tQhi, cx0 + 64,  cy, bar);
        tma2d(stg + 8192,  &tQlo, cx0 + 64,  cy, bar);
        tma2d(stg + 16384, &tQhi, cx0 + 128, cy, bar);
        tma2d(stg + 24576, &tQlo, cx0 + 128, cy, bar);
    };

    for (int r = 0; ; ++r) {
        int slot = (r & 1) ? (G - 1 - (int)blockIdx.x) : (int)blockIdx.x;
        int u = r * G + slot;
        if (u >= NUNITS) break;

        const int qt = (SEQ / 128 - 1) - (u >> 6);
        const int b  = (u >> 4) & 3;
        const int h  = u & 15;
        const int nkt = use_mask ? (2 * qt + 2) : (SEQ / 64);
        const int cx0 = h * 192;
        const int cy0 = b * SEQ;

        if (lane == 0 && wid == 0) {
            if (uc >= 1) mbar_wait_rlx(sb + 24, (uc - 1) & 1);
            mbar_expect(sb, 32768);
            tma2d(sb + AQOFF,         &tQhi, cx0, cy0 + qt * 128,      sb);
            tma2d(sb + AQOFF + 8192,  &tQhi, cx0, cy0 + qt * 128 + 64, sb);
            tma2d(sb + AQOFF + 16384, &tQlo, cx0, cy0 + qt * 128,      sb);
            tma2d(sb + AQOFF + 24576, &tQlo, cx0, cy0 + qt * 128 + 64, sb);
        }
        if (lane == 0 && wid == (int)(icv & 7)) issue_kv(cx0, cy0, icv);
        icv++;

        const uint32_t sQhi = sb + AQOFF, sQlo = sb + AQOFF + 16384;

        float oacc[8][4];
        float m0 = -INFINITY, m1 = -INFINITY, l0 = 0.0f, l1 = 0.0f;
#pragma unroll
        for (int i = 0; i < 8; ++i)
#pragma unroll
            for (int c = 0; c < 4; ++c) oacc[i][c] = 0.0f;

        const int row0 = qt * 128 + wid * 16 + (lane >> 2);
        const int wrow_hi = qt * 128 + wid * 16 + 15;

        mbar_wait(sb, uc & 1);    // Q ready

        for (int kt = 0; kt < nkt; ++kt) {
            if (kt + 1 < nkt) {
                if (lane == 0 && wid == (int)(icv & 7))
                    issue_kv(cx0, cy0 + (kt + 1) * 64, icv);
                icv++;
            }

            const uint32_t cs = ccv & 1;
            mbar_wait(sb + 8 + cs * 8, (ccv >> 1) & 1);
            const uint32_t stg = sb + AKV + cs * AKVST;
            const uint32_t eb  = sb + 32 + cs * 8;
            ccv++;

            if (use_mask && (kt * 64 > wrow_hi)) {
                if (lane == 0) mbar_arrive(eb);
                continue;
            }

            const uint32_t sKhi = stg, sKlo = stg + 8192;
            const uint32_t sVhi = stg + 16384, sVlo = stg + 24576;

            float sacc[8][4];
#pragma unroll
            for (int i = 0; i < 8; ++i)
#pragma unroll
                for (int c = 0; c < 4; ++c) sacc[i][c] = 0.0f;

#pragma unroll
            for (int ks = 0; ks < 4; ++ks) {
                uint32_t ah[4], alr[4];
                {
                    int row = wid * 16 + (lane & 15);
                    uint32_t off = swz128(row, ks * 2 + (lane >> 4));
                    ldsm_x4(ah,  sQhi + off);
                    ldsm_x4(alr, sQlo + off);
                }
#pragma unroll
                for (int nj = 0; nj < 4; ++nj) {
                    // fully-masked 16-col group for this warp: skip (exact —
                    // mask pass below still writes NEG_BIG into the zeros)
                    if (use_mask && (kt * 64 + nj * 16 > wrow_hi)) continue;
                    uint32_t bh[4], bl[4];
                    int row = nj * 16 + (lane & 7) + ((lane >> 4) << 3);
                    uint32_t off = swz128(row, ks * 2 + ((lane >> 3) & 1));
                    ldsm_x4(bh, sKhi + off);
                    ldsm_x4(bl, sKlo + off);
#pragma unroll
                    for (int half = 0; half < 2; ++half) {
                        int nt = nj * 2 + half;
                        mma_bf16(sacc[nt], ah,  bh + half * 2);
                        mma_bf16(sacc[nt], ah,  bl + half * 2);
                        mma_bf16(sacc[nt], alr, bh + half * 2);
                    }
                }
            }

            // scores arrive pre-scaled; causal mask only
            if (use_mask && (kt * 64 + 63 > row0)) {
#pragma unroll
                for (int nt = 0; nt < 8; ++nt) {
                    int col = kt * 64 + nt * 8 + ((lane & 3) << 1);
                    if (col     > row0)     sacc[nt][0] = NEG_BIG;
                    if (col + 1 > row0)     sacc[nt][1] = NEG_BIG;
                    if (col     > row0 + 8) sacc[nt][2] = NEG_BIG;
                    if (col + 1 > row0 + 8) sacc[nt][3] = NEG_BIG;
                }
            }

            float mn0 = m0, mn1 = m1;
#pragma unroll
            for (int nt = 0; nt < 8; ++nt) {
                mn0 = fmaxf(mn0, fmaxf(sacc[nt][0], sacc[nt][1]));
                mn1 = fmaxf(mn1, fmaxf(sacc[nt][2], sacc[nt][3]));
            }
            mn0 = fmaxf(mn0, __shfl_xor_sync(0xffffffffu, mn0, 1));
            mn0 = fmaxf(mn0, __shfl_xor_sync(0xffffffffu, mn0, 2));
            mn1 = fmaxf(mn1, __shfl_xor_sync(0xffffffffu, mn1, 1));
            mn1 = fmaxf(mn1, __shfl_xor_sync(0xffffffffu, mn1, 2));
            float alpha0 = ex2(m0 - mn0);
            float alpha1 = ex2(m1 - mn1);
            m0 = mn0; m1 = mn1;

            float ls0 = 0.0f, ls1 = 0.0f;
#pragma unroll
            for (int nt = 0; nt < 8; ++nt) {
                sacc[nt][0] = ex2(sacc[nt][0] - mn0);
                sacc[nt][1] = ex2(sacc[nt][1] - mn0);
                sacc[nt][2] = ex2(sacc[nt][2] - mn1);
                sacc[nt][3] = ex2(sacc[nt][3] - mn1);
                ls0 += sacc[nt][0] + sacc[nt][1];
                ls1 += sacc[nt][2] + sacc[nt][3];
            }
            ls0 += __shfl_xor_sync(0xffffffffu, ls0, 1);
            ls0 += __shfl_xor_sync(0xffffffffu, ls0, 2);
            ls1 += __shfl_xor_sync(0xffffffffu, ls1, 1);
            ls1 += __shfl_xor_sync(0xffffffffu, ls1, 2);
            l0 = l0 * alpha0 + ls0;
            l1 = l1 * alpha1 + ls1;
#pragma unroll
            for (int nt = 0; nt < 8; ++nt) {
                oacc[nt][0] *= alpha0; oacc[nt][1] *= alpha0;
                oacc[nt][2] *= alpha1; oacc[nt][3] *= alpha1;
            }

#pragma unroll
            for (int t = 0; t < 4; ++t) {
                // P columns for this t-group are exactly zero if fully masked
                if (use_mask && (kt * 64 + t * 16 > wrow_hi)) continue;
                uint32_t ap[4], apl[4];
                packsplit(sacc[2*t][0],   sacc[2*t][1],   ap[0], apl[0]);
                packsplit(sacc[2*t][2],   sacc[2*t][3],   ap[1], apl[1]);
                packsplit(sacc[2*t+1][0], sacc[2*t+1][1], ap[2], apl[2]);
                packsplit(sacc[2*t+1][2], sacc[2*t+1][3], ap[3], apl[3]);
#pragma unroll
                for (int nt2 = 0; nt2 < 4; ++nt2) {
                    uint32_t bv[4], bvl[4];
                    int row = t * 16 + (lane & 15);
                    uint32_t off = swz128(row, nt2 * 2 + (lane >> 4));
                    ldsm_x4t(bv,  sVhi + off);
                    ldsm_x4t(bvl, sVlo + off);
                    mma_bf16(oacc[2*nt2],   ap,  bv);
                    mma_bf16(oacc[2*nt2],   ap,  bvl);
                    mma_bf16(oacc[2*nt2],   apl, bv);
                    mma_bf16(oacc[2*nt2+1], ap,  bv + 2);
                    mma_bf16(oacc[2*nt2+1], ap,  bvl + 2);
                    mma_bf16(oacc[2*nt2+1], apl, bv + 2);
                }
            }

            if (lane == 0) mbar_arrive(eb);
        }

        if (lane == 0) mbar_arrive(sb + 24);
        uc++;

        float il0 = 1.0f / l0, il1 = 1.0f / l1;
        const size_t rb = ((size_t)(b * NHEAD + h) * SEQ + qt * 128 + wid * 16);
        const int er = lane >> 2, ec = (lane & 3) << 1;
#pragma unroll
        for (int nt = 0; nt < 8; ++nt) {
            uint32_t hv, lv;
            size_t p0 = (rb + er) * HDIM + nt * 8 + ec;
            packsplit(oacc[nt][0] * il0, oacc[nt][1] * il0, hv, lv);
            *(uint32_t*)(ohi + p0) = hv;
            *(uint32_t*)(olo + p0) = lv;
            size_t p1 = (rb + er + 8) * HDIM + nt * 8 + ec;
            packsplit(oacc[nt][2] * il1, oacc[nt][3] * il1, hv, lv);
            *(uint32_t*)(ohi + p1) = hv;
            *(uint32_t*)(olo + p1) = lv;
        }
    }
}

// ---------------------------------------------------------------------------
// Host: tensormap construction + launch
// ---------------------------------------------------------------------------
typedef CUresult (*PFN_tmEncode)(
    CUtensorMap*, CUtensorMapDataType, cuuint32_t, void*,
    const cuuint64_t*, const cuuint64_t*, const cuuint32_t*, const cuuint32_t*,
    CUtensorMapInterleave, CUtensorMapSwizzle, CUtensorMapL2promotion,
    CUtensorMapFloatOOBfill);

static void make2d(PFN_tmEncode enc, CUtensorMap* m, void* p,
                   uint64_t d0, uint64_t d1, uint64_t stride1,
                   uint32_t b0, uint32_t b1, CUtensorMapSwizzle sw)
{
    cuuint64_t dims[2] = {d0, d1};
    cuuint64_t strides[1] = {stride1};
    cuuint32_t box[2] = {b0, b1};
    cuuint32_t es[2] = {1, 1};
    enc(m, CU_TENSOR_MAP_DATA_TYPE_BFLOAT16, 2, p, dims, strides, box, es,
        CU_TENSOR_MAP_INTERLEAVE_NONE, sw, CU_TENSOR_MAP_L2_PROMOTION_L2_128B,
        CU_TENSOR_MAP_FLOAT_OOB_FILL_NONE);
}

extern "C" void kernel_launch(void* const* d_in, const int* in_sizes, int n_in,
                              void* d_out, int out_size)
{
    const float* x     = (const float*)d_in[0];
    const float* W_qkv = (const float*)d_in[1];
    const float* b_qkv = (const float*)d_in[2];
    const float* W_out = (const float*)d_in[3];
    const float* b_out = (const float*)d_in[4];
    const int*   maskp = (const int*)d_in[5];
    float* outp = (float*)d_out;

    __nv_bfloat16 *qkvhi, *qkvlo, *xhi, *xlo, *w1hi, *w1lo, *w2hi, *w2lo, *ohi, *olo;
    cudaGetSymbolAddress((void**)&qkvhi, g_qkvhi);
    cudaGetSymbolAddress((void**)&qkvlo, g_qkvlo);
    cudaGetSymbolAddress((void**)&xhi,  g_xhi);
    cudaGetSymbolAddress((void**)&xlo,  g_xlo);
    cudaGetSymbolAddress((void**)&w1hi, g_w1hi);
    cudaGetSymbolAddress((void**)&w1lo, g_w1lo);
    cudaGetSymbolAddress((void**)&w2hi, g_w2hi);
    cudaGetSymbolAddress((void**)&w2lo, g_w2lo);
    cudaGetSymbolAddress((void**)&ohi,  g_ohi);
    cudaGetSymbolAddress((void**)&olo,  g_olo);

    PFN_tmEncode enc = nullptr;
    {
        void* fn = nullptr;
        cudaDriverEntryPointQueryResult qr;
        cudaGetDriverEntryPoint("cuTensorMapEncodeTiled", &fn,
                                cudaEnableDefault, &qr);
        enc = (PFN_tmEncode)fn;
    }

    CUtensorMap tXhi, tXlo, tW1hi, tW1lo, tOhi, tOlo, tW2hi, tW2lo, tQhi, tQlo;
    make2d(enc, &tXhi,  xhi,  DMODEL, MTOT,   DMODEL * 2, 32, 128, CU_TENSOR_MAP_SWIZZLE_64B);
    make2d(enc, &tXlo,  xlo,  DMODEL, MTOT,   DMODEL * 2, 32, 128, CU_TENSOR_MAP_SWIZZLE_64B);
    make2d(enc, &tW1hi, w1hi, DMODEL, TD,     DMODEL * 2, 32, 128, CU_TENSOR_MAP_SWIZZLE_64B);
    make2d(enc, &tW1lo, w1lo, DMODEL, TD,     DMODEL * 2, 32, 128, CU_TENSOR_MAP_SWIZZLE_64B);
    make2d(enc, &tOhi,  ohi,  DMODEL, MTOT,   DMODEL * 2, 32, 128, CU_TENSOR_MAP_SWIZZLE_64B);
    make2d(enc, &tOlo,  olo,  DMODEL, MTOT,   DMODEL * 2, 32, 128, CU_TENSOR_MAP_SWIZZLE_64B);
    make2d(enc, &tW2hi, w2hi, DMODEL, DMODEL, DMODEL * 2, 32, 128, CU_TENSOR_MAP_SWIZZLE_64B);
    make2d(enc, &tW2lo, w2lo, DMODEL, DMODEL, DMODEL * 2, 32, 128, CU_TENSOR_MAP_SWIZZLE_64B);
    make2d(enc, &tQhi,  qkvhi, TD, MTOT, TD * 2, 64, 64, CU_TENSOR_MAP_SWIZZLE_128B);
    make2d(enc, &tQlo,  qkvlo, TD, MTOT, TD * 2, 64, 64, CU_TENSOR_MAP_SWIZZLE_128B);

    cudaFuncSetAttribute(gemm_bf16x3,
                         cudaFuncAttributeMaxDynamicSharedMemorySize, GSMEM);
    cudaFuncSetAttribute(gemm_bf16x3,
                         cudaFuncAttributePreferredSharedMemoryCarveout, 100);
    cudaFuncSetAttribute(attn_flash_hmma,
                         cudaFuncAttributeMaxDynamicSharedMemorySize, ASMEM);
    cudaFuncSetAttribute(attn_flash_hmma,
                         cudaFuncAttributePreferredSharedMemoryCarveout, 100);

    // 1) fused prep
    prep_kernel<<<PREP_BLKS, 256>>>(x, xhi, xlo, W_qkv, w1hi, w1lo,
                                    W_out, w2hi, w2lo);

    // 2) QKV projection (persistent)
    {
        int nbx = TD / 128, ntiles = nbx * (MTOT / 128);
        gemm_bf16x3<<<NSM_X2, 256, GSMEM>>>(tXhi, tXlo, tW1hi, tW1lo, b_qkv,
                                            nullptr, qkvhi, qkvlo, 1,
                                            MTOT, TD, DMODEL, ntiles, nbx);
    }
    // 3) flash attention (persistent, balanced schedule)
    attn_flash_hmma<<<NSM_X2, 256, ASMEM>>>(tQhi, tQlo, ohi, olo, maskp);

    // 4) output projection (persistent)
    {
        int nbx = DMODEL / 128, ntiles = nbx * (MTOT / 128);
        gemm_bf16x3<<<NSM_X2, 256, GSMEM>>>(tOhi, tOlo, tW2hi, tW2lo, b_out,
                                            outp, nullptr, nullptr, 0,
                                            MTOT, DMODEL, DMODEL, ntiles, nbx);
    }
}

// round 16
// speedup vs baseline: 1.0163x; 1.0163x over previous
#include <cuda_runtime.h>
#include <cuda.h>
#include <cuda_bf16.h>
#include <cstdint>

// ---------------------------------------------------------------------------
// Problem constants: B=4, S=2048, D=1024, H=16, hd=64, causal mask
// ---------------------------------------------------------------------------
#define BATCH 4
#define SEQ   2048
#define DMODEL 1024
#define NHEAD 16
#define HDIM  64
#define TD    (3 * DMODEL)          // 3072
#define MTOT  (BATCH * SEQ)         // 8192
#define NEG_BIG -1e30f
#define NSM_X2 304
#define EXSCALE (0.125f * 1.44269504f)   // 1/sqrt(64) * log2(e)

// Scratch (__device__ globals — allocation-free rule)
__device__ __nv_bfloat16 g_qkvhi[(size_t)MTOT * TD];
__device__ __nv_bfloat16 g_qkvlo[(size_t)MTOT * TD];
__device__ __nv_bfloat16 g_xhi[(size_t)MTOT * DMODEL];
__device__ __nv_bfloat16 g_xlo[(size_t)MTOT * DMODEL];
__device__ __nv_bfloat16 g_w1hi[(size_t)TD * DMODEL];
__device__ __nv_bfloat16 g_w1lo[(size_t)TD * DMODEL];
__device__ __nv_bfloat16 g_w2hi[(size_t)DMODEL * DMODEL];
__device__ __nv_bfloat16 g_w2lo[(size_t)DMODEL * DMODEL];
__device__ __nv_bfloat16 g_ohi[(size_t)MTOT * DMODEL];
__device__ __nv_bfloat16 g_olo[(size_t)MTOT * DMODEL];

// ---------------------------------------------------------------------------
// helpers
// ---------------------------------------------------------------------------
__device__ __forceinline__ void ldsm_x4(uint32_t* r, uint32_t addr) {
    asm volatile("ldmatrix.sync.aligned.m8n8.x4.shared.b16 {%0,%1,%2,%3}, [%4];"
                 : "=r"(r[0]), "=r"(r[1]), "=r"(r[2]), "=r"(r[3]) : "r"(addr));
}
__device__ __forceinline__ void ldsm_x4t(uint32_t* r, uint32_t addr) {
    asm volatile("ldmatrix.sync.aligned.m8n8.x4.trans.shared.b16 {%0,%1,%2,%3}, [%4];"
                 : "=r"(r[0]), "=r"(r[1]), "=r"(r[2]), "=r"(r[3]) : "r"(addr));
}
__device__ __forceinline__ void mma_bf16(float* d, const uint32_t* a, const uint32_t* b) {
    asm volatile("mma.sync.aligned.m16n8k16.row.col.f32.bf16.bf16.f32 "
                 "{%0,%1,%2,%3}, {%4,%5,%6,%7}, {%8,%9}, {%0,%1,%2,%3};"
                 : "+f"(d[0]), "+f"(d[1]), "+f"(d[2]), "+f"(d[3])
                 : "r"(a[0]), "r"(a[1]), "r"(a[2]), "r"(a[3]),
                   "r"(b[0]), "r"(b[1]));
}
__device__ __forceinline__ float ex2(float x) {
    float r;
    asm("ex2.approx.f32 %0, %1;" : "=f"(r) : "f"(x));
    return r;
}
__device__ __forceinline__ void packsplit(float v0, float v1, uint32_t& hi, uint32_t& lo) {
    __nv_bfloat162 hp = __float22bfloat162_rn(make_float2(v0, v1));
    hi = *reinterpret_cast<uint32_t*>(&hp);
    __nv_bfloat162 lp = __float22bfloat162_rn(make_float2(
        v0 - __bfloat162float(hp.x), v1 - __bfloat162float(hp.y)));
    lo = *reinterpret_cast<uint32_t*>(&lp);
}
// 64B rows (GEMM BK=32): matches CU_TENSOR_MAP_SWIZZLE_64B
__device__ __forceinline__ uint32_t swz(int row, int gran) {
    return (uint32_t)(row * 64 + ((gran ^ ((row >> 1) & 3)) << 4));
}
// 128B rows (attention hd=64): matches CU_TENSOR_MAP_SWIZZLE_128B
__device__ __forceinline__ uint32_t swz128(int row, int gran) {
    return (uint32_t)(row * 128 + ((gran ^ (row & 7)) << 4));
}
__device__ __forceinline__ void tma2d(uint32_t dst, const CUtensorMap* m,
                                      int cx, int cy, uint32_t mbar) {
    asm volatile(
        "cp.async.bulk.tensor.2d.shared::cta.global.tile.mbarrier::complete_tx::bytes "
        "[%0], [%1, {%2, %3}], [%4];"
        :: "r"(dst), "l"(m), "r"(cx), "r"(cy), "r"(mbar) : "memory");
}
__device__ __forceinline__ void mbar_init(uint32_t mbar, uint32_t cnt) {
    asm volatile("mbarrier.init.shared.b64 [%0], %1;" :: "r"(mbar), "r"(cnt) : "memory");
}
__device__ __forceinline__ void mbar_expect(uint32_t mbar, uint32_t bytes) {
    asm volatile("mbarrier.arrive.expect_tx.shared.b64 _, [%0], %1;"
                 :: "r"(mbar), "r"(bytes) : "memory");
}
__device__ __forceinline__ void mbar_arrive(uint32_t mbar) {
    asm volatile("mbarrier.arrive.shared.b64 _, [%0];" :: "r"(mbar) : "memory");
}
// acquire wait — consumer side (generic smem reads follow)
__device__ __forceinline__ void mbar_wait(uint32_t mbar, uint32_t parity) {
    uint32_t done;
    do {
        asm volatile(
            "{\n\t.reg .pred p;\n\t"
            "mbarrier.try_wait.parity.acquire.cta.shared::cta.b64 p, [%1], %2, 0x989680;\n\t"
            "selp.b32 %0, 1, 0, p;\n\t}"
            : "=r"(done) : "r"(mbar), "r"(parity) : "memory");
    } while (!done);
}
// relaxed wait — producer side ONLY (post-wait accesses are async-proxy TMA)
__device__ __forceinline__ void mbar_wait_rlx(uint32_t mbar, uint32_t parity) {
    uint32_t done;
    do {
        asm volatile(
            "{\n\t.reg .pred p;\n\t"
            "mbarrier.try_wait.parity.relaxed.cta.shared::cta.b64 p, [%1], %2, 0x989680;\n\t"
            "selp.b32 %0, 1, 0, p;\n\t}"
            : "=r"(done) : "r"(mbar), "r"(parity) : "memory");
    } while (!done);
}

// ---------------------------------------------------------------------------
// Fused prep: phase 0 split x, phase 1 transpose+split W_qkv, phase 2 W_out
// ---------------------------------------------------------------------------
#define SPLIT_BLKS (MTOT * DMODEL / 4 / 256)            // 8192
#define T1_BX (TD / 32)                                 // 96
#define T1_BLKS (T1_BX * (DMODEL / 32))                 // 3072
#define T2_BX (DMODEL / 32)                             // 32
#define T2_BLKS (T2_BX * (DMODEL / 32))                 // 1024
#define PREP_BLKS (SPLIT_BLKS + T1_BLKS + T2_BLKS)

__device__ __forceinline__ void do_transpose_split(
    const float* __restrict__ W, __nv_bfloat16* __restrict__ bhi,
    __nv_bfloat16* __restrict__ blo, int K, int N, int bidx, int bx_count)
{
    __shared__ float t[32][33];
    int nb = (bidx % bx_count) * 32, kb = (bidx / bx_count) * 32;
    int tx = threadIdx.x & 31, ty = threadIdx.x >> 5;
#pragma unroll
    for (int i = 0; i < 4; ++i)
        t[ty + i * 8][tx] = W[(size_t)(kb + ty + i * 8) * N + nb + tx];
    __syncthreads();
#pragma unroll
    for (int i = 0; i < 4; ++i) {
        int n = nb + ty + i * 8;
        int k = kb + tx;
        float v = t[tx][ty + i * 8];
        __nv_bfloat16 h = __float2bfloat16(v);
        bhi[(size_t)n * K + k] = h;
        blo[(size_t)n * K + k] = __float2bfloat16(v - __bfloat162float(h));
    }
}

__global__ __launch_bounds__(256) void prep_kernel(
    const float* __restrict__ x,
    __nv_bfloat16* __restrict__ xhi, __nv_bfloat16* __restrict__ xlo,
    const float* __restrict__ W1, __nv_bfloat16* __restrict__ w1hi,
    __nv_bfloat16* __restrict__ w1lo,
    const float* __restrict__ W2, __nv_bfloat16* __restrict__ w2hi,
    __nv_bfloat16* __restrict__ w2lo)
{
    int bid = blockIdx.x;
    if (bid < SPLIT_BLKS) {
        int i = bid * 256 + threadIdx.x;
        float4 v = ((const float4*)x)[i];
        uint32_t h0, l0, h1, l1;
        packsplit(v.x, v.y, h0, l0);
        packsplit(v.z, v.w, h1, l1);
        ((uint32_t*)xhi)[2*i] = h0; ((uint32_t*)xhi)[2*i+1] = h1;
        ((uint32_t*)xlo)[2*i] = l0; ((uint32_t*)xlo)[2*i+1] = l1;
    } else if (bid < SPLIT_BLKS + T1_BLKS) {
        do_transpose_split(W1, w1hi, w1lo, DMODEL, TD, bid - SPLIT_BLKS, T1_BX);
    } else {
        do_transpose_split(W2, w2hi, w2lo, DMODEL, DMODEL,
                           bid - SPLIT_BLKS - T1_BLKS, T2_BX);
    }
}

// ---------------------------------------------------------------------------
// bf16x3 HMMA GEMM: 128x128 tile, BK=32, 8 warps, TMA + full/empty mbarrier
// pipeline (3 stages), flat chunk stream across tiles, NO __syncthreads in
// the mainloop.  Producer duty distributed: chunk j issued by warp (j&7).
// ---------------------------------------------------------------------------
#define GSTAGE 32768
#define GSMEM (1024 + 3 * GSTAGE)       // 99328

__global__ __launch_bounds__(256, 2) void gemm_bf16x3(
    const __grid_constant__ CUtensorMap tAhi, const __grid_constant__ CUtensorMap tAlo,
    const __grid_constant__ CUtensorMap tBhi, const __grid_constant__ CUtensorMap tBlo,
    const float* __restrict__ bias, float* __restrict__ C,
    __nv_bfloat16* __restrict__ Chi, __nv_bfloat16* __restrict__ Clo,
    int bf16out, int M, int N, int K, int NTILES, int NBX)
{
    extern __shared__ char smraw[];
    char* smem = (char*)(((uintptr_t)smraw + 1023) & ~(uintptr_t)1023);
    const uint32_t sb = (uint32_t)__cvta_generic_to_shared(smem);
    const uint32_t tiles = sb + 1024;

    const int tid  = threadIdx.x;
    const int wid  = tid >> 5;
    const int lane = tid & 31;
    const int wm   = wid >> 2;
    const int wn   = wid & 3;
    const int NC = K >> 5;

    if (tid == 0) {
        mbar_init(sb + 0, 1);  mbar_init(sb + 8, 1);  mbar_init(sb + 16, 1);
        mbar_init(sb + 24, 8); mbar_init(sb + 32, 8); mbar_init(sb + 40, 8);
    }
    __syncthreads();

    int ntile = (NTILES - (int)blockIdx.x + (int)gridDim.x - 1) / (int)gridDim.x;
    if (ntile < 0) ntile = 0;
    const int total = ntile * NC;

    auto issue = [&](int j) {
        int tix = (int)blockIdx.x + (j / NC) * (int)gridDim.x;
        int kc = (j % NC) << 5;
        int im0 = (tix / NBX) * 128;
        int in0 = (tix % NBX) * 128;
        uint32_t s = (uint32_t)(j % 3);
        if (j >= 3) mbar_wait_rlx(sb + 24 + s * 8, (uint32_t)((j / 3 - 1) & 1));
        uint32_t stg = tiles + s * GSTAGE;
        uint32_t bar = sb + s * 8;
        mbar_expect(bar, 32768);
        tma2d(stg,         &tAhi, kc, im0, bar);
        tma2d(stg + 8192,  &tAlo, kc, im0, bar);
        tma2d(stg + 16384, &tBhi, kc, in0, bar);
        tma2d(stg + 24576, &tBlo, kc, in0, bar);
    };

    if (lane == 0) {
        if (wid == 0 && total > 0) issue(0);
        if (wid == 1 && total > 1) issue(1);
    }

    float acc[4][4][4];
    int jn = 0;
    int tix = (int)blockIdx.x;

    for (int j = 0; j < total; ++j) {
        const int m0 = (tix / NBX) * 128;
        const int n0 = (tix % NBX) * 128;

        if (jn == 0) {
#pragma unroll
            for (int i = 0; i < 4; ++i)
#pragma unroll
                for (int jj = 0; jj < 4; ++jj)
#pragma unroll
                    for (int c = 0; c < 4; ++c) acc[i][jj][c] = 0.0f;
        }

        if (lane == 0 && wid == ((j + 2) & 7) && j + 2 < total) issue(j + 2);

        const uint32_t s = (uint32_t)(j % 3);
        mbar_wait(sb + s * 8, (uint32_t)((j / 3) & 1));

        const uint32_t st = tiles + s * GSTAGE;
        const uint32_t sAhi = st, sAlo = st + 8192,
                       sBhi = st + 16384, sBlo = st + 24576;

#pragma unroll
        for (int kk = 0; kk < 2; ++kk) {
            uint32_t ah[4][4], al[4][4], bh[2][4], bl[2][4];
#pragma unroll
            for (int mi = 0; mi < 4; ++mi) {
                int row = wm * 64 + mi * 16 + (lane & 15);
                uint32_t off = swz(row, kk * 2 + (lane >> 4));
                ldsm_x4(ah[mi], sAhi + off);
                ldsm_x4(al[mi], sAlo + off);
            }
#pragma unroll
            for (int nj = 0; nj < 2; ++nj) {
                int row = wn * 32 + nj * 16 + (lane & 7) + ((lane >> 4) << 3);
                uint32_t off = swz(row, kk * 2 + ((lane >> 3) & 1));
                ldsm_x4(bh[nj], sBhi + off);
                ldsm_x4(bl[nj], sBlo + off);
            }
#pragma unroll
            for (int mi = 0; mi < 4; ++mi)
#pragma unroll
                for (int ni = 0; ni < 4; ++ni) {
                    const uint32_t* pbh = bh[ni >> 1] + (ni & 1) * 2;
                    const uint32_t* pbl = bl[ni >> 1] + (ni & 1) * 2;
                    mma_bf16(acc[mi][ni], ah[mi], pbh);
                    mma_bf16(acc[mi][ni], ah[mi], pbl);
                    mma_bf16(acc[mi][ni], al[mi], pbh);
                }
        }

        if (lane == 0) mbar_arrive(sb + 24 + s * 8);

        if (jn == NC - 1) {
            const int rbase = m0 + wm * 64 + (lane >> 2);
            const int cbase = n0 + wn * 32 + ((lane & 3) << 1);
#pragma unroll
            for (int mi = 0; mi < 4; ++mi)
#pragma unroll
                for (int ni = 0; ni < 4; ++ni) {
                    int r = rbase + mi * 16;
                    int c = cbase + ni * 8;
                    float b0 = bias[c], b1 = bias[c + 1];
                    float v0 = acc[mi][ni][0] + b0, v1 = acc[mi][ni][1] + b1;
                    float v2 = acc[mi][ni][2] + b0, v3 = acc[mi][ni][3] + b1;
                    if (!bf16out) {
                        *(float2*)(C + (size_t)r * N + c)       = make_float2(v0, v1);
                        *(float2*)(C + (size_t)(r + 8) * N + c) = make_float2(v2, v3);
                    } else {
                        float sc = ((c % 192) < 64) ? EXSCALE : 1.0f;
                        v0 *= sc; v1 *= sc; v2 *= sc; v3 *= sc;
                        uint32_t h, l;
                        packsplit(v0, v1, h, l);
                        *(uint32_t*)(Chi + (size_t)r * N + c) = h;
                        *(uint32_t*)(Clo + (size_t)r * N + c) = l;
                        packsplit(v2, v3, h, l);
                        *(uint32_t*)(Chi + (size_t)(r + 8) * N + c) = h;
                        *(uint32_t*)(Clo + (size_t)(r + 8) * N + c) = l;
                    }
                }
        }

        if (++jn == NC) { jn = 0; tix += (int)gridDim.x; }
    }
}

// ---------------------------------------------------------------------------
// Flash attention: persistent boustrophedon schedule, TMA + full/empty
// mbarrier pipeline (Q pair + 2 KV stage pairs), NO mainloop __syncthreads.
// Whole-tile causal skip only (fine-grained skip reverted — round 15 lesson).
// ---------------------------------------------------------------------------
#define AQOFF 1024
#define AKV   (1024 + 32768)
#define AKVST 32768
#define ASMEM (1024 + 32768 + 2 * 32768)   // 99328
#define NUNITS ((SEQ / 128) * NHEAD * BATCH)

__global__ __launch_bounds__(256, 2) void attn_flash_hmma(
    const __grid_constant__ CUtensorMap tQhi, const __grid_constant__ CUtensorMap tQlo,
    __nv_bfloat16* __restrict__ ohi, __nv_bfloat16* __restrict__ olo,
    const int* __restrict__ maskp)
{
    extern __shared__ char smraw[];
    char* smem = (char*)(((uintptr_t)smraw + 1023) & ~(uintptr_t)1023);
    const uint32_t sb = (uint32_t)__cvta_generic_to_shared(smem);

    const int tid  = threadIdx.x;
    const int wid  = tid >> 5;
    const int lane = tid & 31;
    const int use_mask = (maskp[0] != 0);
    const int G = (int)gridDim.x;

    if (tid == 0) {
        mbar_init(sb + 0, 1);    // Q full
        mbar_init(sb + 8, 1);    // KV full 0
        mbar_init(sb + 16, 1);   // KV full 1
        mbar_init(sb + 24, 8);   // Q empty
        mbar_init(sb + 32, 8);   // KV empty 0
        mbar_init(sb + 40, 8);   // KV empty 1
    }
    __syncthreads();

    uint32_t uc = 0;
    uint32_t icv = 0, ccv = 0;

    auto issue_kv = [&](int cx0, int cy, uint32_t j) {
        uint32_t s = j & 1;
        if (j >= 2) mbar_wait_rlx(sb + 32 + s * 8, ((j >> 1) - 1) & 1);
        uint32_t stg = sb + AKV + s * AKVST;
        uint32_t bar = sb + 8 + s * 8;
        mbar_expect(bar, 32768);
        tma2d(stg,         &tQhi, cx0 + 64,  cy, bar);
        tma2d(stg + 8192,  &tQlo, cx0 + 64,  cy, bar);
        tma2d(stg + 16384, &tQhi, cx0 + 128, cy, bar);
        tma2d(stg + 24576, &tQlo, cx0 + 128, cy, bar);
    };

    for (int r = 0; ; ++r) {
        int slot = (r & 1) ? (G - 1 - (int)blockIdx.x) : (int)blockIdx.x;
        int u = r * G + slot;
        if (u >= NUNITS) break;

        const int qt = (SEQ / 128 - 1) - (u >> 6);
        const int b  = (u >> 4) & 3;
        const int h  = u & 15;
        const int nkt = use_mask ? (2 * qt + 2) : (SEQ / 64);
        const int cx0 = h * 192;
        const int cy0 = b * SEQ;

        if (lane == 0 && wid == 0) {
            if (uc >= 1) mbar_wait_rlx(sb + 24, (uc - 1) & 1);
            mbar_expect(sb, 32768);
            tma2d(sb + AQOFF,         &tQhi, cx0, cy0 + qt * 128,      sb);
            tma2d(sb + AQOFF + 8192,  &tQhi, cx0, cy0 + qt * 128 + 64, sb);
            tma2d(sb + AQOFF + 16384, &tQlo, cx0, cy0 + qt * 128,      sb);
            tma2d(sb + AQOFF + 24576, &tQlo, cx0, cy0 + qt * 128 + 64, sb);
        }
        if (lane == 0 && wid == (int)(icv & 7)) issue_kv(cx0, cy0, icv);
        icv++;

        const uint32_t sQhi = sb + AQOFF, sQlo = sb + AQOFF + 16384;

        float oacc[8][4];
        float m0 = -INFINITY, m1 = -INFINITY, l0 = 0.0f, l1 = 0.0f;
#pragma unroll
        for (int i = 0; i < 8; ++i)
#pragma unroll
            for (int c = 0; c < 4; ++c) oacc[i][c] = 0.0f;

        const int row0 = qt * 128 + wid * 16 + (lane >> 2);
        const int wrow_hi = qt * 128 + wid * 16 + 15;

        mbar_wait(sb, uc & 1);    // Q ready

        for (int kt = 0; kt < nkt; ++kt) {
            if (kt + 1 < nkt) {
                if (lane == 0 && wid == (int)(icv & 7))
                    issue_kv(cx0, cy0 + (kt + 1) * 64, icv);
                icv++;
            }

            const uint32_t cs = ccv & 1;
            mbar_wait(sb + 8 + cs * 8, (ccv >> 1) & 1);
            const uint32_t stg = sb + AKV + cs * AKVST;
            const uint32_t eb  = sb + 32 + cs * 8;
            ccv++;

            if (use_mask && (kt * 64 > wrow_hi)) {
                if (lane == 0) mbar_arrive(eb);
                continue;
            }

            const uint32_t sKhi = stg, sKlo = stg + 8192;
            const uint32_t sVhi = stg + 16384, sVlo = stg + 24576;

            float sacc[8][4];
#pragma unroll
            for (int i = 0; i < 8; ++i)
#pragma unroll
                for (int c = 0; c < 4; ++c) sacc[i][c] = 0.0f;

#pragma unroll
            for (int ks = 0; ks < 4; ++ks) {
                uint32_t ah[4], alr[4];
                {
                    int row = wid * 16 + (lane & 15);
                    uint32_t off = swz128(row, ks * 2 + (lane >> 4));
                    ldsm_x4(ah,  sQhi + off);
                    ldsm_x4(alr, sQlo + off);
                }
#pragma unroll
                for (int nj = 0; nj < 4; ++nj) {
                    uint32_t bh[4], bl[4];
                    int row = nj * 16 + (lane & 7) + ((lane >> 4) << 3);
                    uint32_t off = swz128(row, ks * 2 + ((lane >> 3) & 1));
                    ldsm_x4(bh, sKhi + off);
                    ldsm_x4(bl, sKlo + off);
#pragma unroll
                    for (int half = 0; half < 2; ++half) {
                        int nt = nj * 2 + half;
                        mma_bf16(sacc[nt], ah,  bh + half * 2);
                        mma_bf16(sacc[nt], ah,  bl + half * 2);
                        mma_bf16(sacc[nt], alr, bh + half * 2);
                    }
                }
            }

            // scores arrive pre-scaled; causal mask only
            if (use_mask && (kt * 64 + 63 > row0)) {
#pragma unroll
                for (int nt = 0; nt < 8; ++nt) {
                    int col = kt * 64 + nt * 8 + ((lane & 3) << 1);
                    if (col     > row0)     sacc[nt][0] = NEG_BIG;
                    if (col + 1 > row0)     sacc[nt][1] = NEG_BIG;
                    if (col     > row0 + 8) sacc[nt][2] = NEG_BIG;
                    if (col + 1 > row0 + 8) sacc[nt][3] = NEG_BIG;
                }
            }

            float mn0 = m0, mn1 = m1;
#pragma unroll
            for (int nt = 0; nt < 8; ++nt) {
                mn0 = fmaxf(mn0, fmaxf(sacc[nt][0], sacc[nt][1]));
                mn1 = fmaxf(mn1, fmaxf(sacc[nt][2], sacc[nt][3]));
            }
            mn0 = fmaxf(mn0, __shfl_xor_sync(0xffffffffu, mn0, 1));
            mn0 = fmaxf(mn0, __shfl_xor_sync(0xffffffffu, mn0, 2));
            mn1 = fmaxf(mn1, __shfl_xor_sync(0xffffffffu, mn1, 1));
            mn1 = fmaxf(mn1, __shfl_xor_sync(0xffffffffu, mn1, 2));
            float alpha0 = ex2(m0 - mn0);
            float alpha1 = ex2(m1 - mn1);
            m0 = mn0; m1 = mn1;

            float ls0 = 0.0f, ls1 = 0.0f;
#pragma unroll
            for (int nt = 0; nt < 8; ++nt) {
                sacc[nt][0] = ex2(sacc[nt][0] - mn0);
                sacc[nt][1] = ex2(sacc[nt][1] - mn0);
                sacc[nt][2] = ex2(sacc[nt][2] - mn1);
                sacc[nt][3] = ex2(sacc[nt][3] - mn1);
                ls0 += sacc[nt][0] + sacc[nt][1];
                ls1 += sacc[nt][2] + sacc[nt][3];
            }
            ls0 += __shfl_xor_sync(0xffffffffu, ls0, 1);
            ls0 += __shfl_xor_sync(0xffffffffu, ls0, 2);
            ls1 += __shfl_xor_sync(0xffffffffu, ls1, 1);
            ls1 += __shfl_xor_sync(0xffffffffu, ls1, 2);
            l0 = l0 * alpha0 + ls0;
            l1 = l1 * alpha1 + ls1;
#pragma unroll
            for (int nt = 0; nt < 8; ++nt) {
                oacc[nt][0] *= alpha0; oacc[nt][1] *= alpha0;
                oacc[nt][2] *= alpha1; oacc[nt][3] *= alpha1;
            }

#pragma unroll
            for (int t = 0; t < 4; ++t) {
                uint32_t ap[4], apl[4];
                packsplit(sacc[2*t][0],   sacc[2*t][1],   ap[0], apl[0]);
                packsplit(sacc[2*t][2],   sacc[2*t][3],   ap[1], apl[1]);
                packsplit(sacc[2*t+1][0], sacc[2*t+1][1], ap[2], apl[2]);
                packsplit(sacc[2*t+1][2], sacc[2*t+1][3], ap[3], apl[3]);
#pragma unroll
                for (int nt2 = 0; nt2 < 4; ++nt2) {
                    uint32_t bv[4], bvl[4];
                    int row = t * 16 + (lane & 15);
                    uint32_t off = swz128(row, nt2 * 2 + (lane >> 4));
                    ldsm_x4t(bv,  sVhi + off);
                    ldsm_x4t(bvl, sVlo + off);
                    mma_bf16(oacc[2*nt2],   ap,  bv);
                    mma_bf16(oacc[2*nt2],   ap,  bvl);
                    mma_bf16(oacc[2*nt2],   apl, bv);
                    mma_bf16(oacc[2*nt2+1], ap,  bv + 2);
                    mma_bf16(oacc[2*nt2+1], ap,  bvl + 2);
                    mma_bf16(oacc[2*nt2+1], apl, bv + 2);
                }
            }

            if (lane == 0) mbar_arrive(eb);
        }

        if (lane == 0) mbar_arrive(sb + 24);
        uc++;

        float il0 = 1.0f / l0, il1 = 1.0f / l1;
        const size_t rb = ((size_t)(b * NHEAD + h) * SEQ + qt * 128 + wid * 16);
        const int er = lane >> 2, ec = (lane & 3) << 1;
#pragma unroll
        for (int nt = 0; nt < 8; ++nt) {
            uint32_t hv, lv;
            size_t p0 = (rb + er) * HDIM + nt * 8 + ec;
            packsplit(oacc[nt][0] * il0, oacc[nt][1] * il0, hv, lv);
            *(uint32_t*)(ohi + p0) = hv;
            *(uint32_t*)(olo + p0) = lv;
            size_t p1 = (rb + er + 8) * HDIM + nt * 8 + ec;
            packsplit(oacc[nt][2] * il1, oacc[nt][3] * il1, hv, lv);
            *(uint32_t*)(ohi + p1) = hv;
            *(uint32_t*)(olo + p1) = lv;
        }
    }
}

// ---------------------------------------------------------------------------
// Host: tensormap construction + launch
// ---------------------------------------------------------------------------
typedef CUresult (*PFN_tmEncode)(
    CUtensorMap*, CUtensorMapDataType, cuuint32_t, void*,
    const cuuint64_t*, const cuuint64_t*, const cuuint32_t*, const cuuint32_t*,
    CUtensorMapInterleave, CUtensorMapSwizzle, CUtensorMapL2promotion,
    CUtensorMapFloatOOBfill);

static void make2d(PFN_tmEncode enc, CUtensorMap* m, void* p,
                   uint64_t d0, uint64_t d1, uint64_t stride1,
                   uint32_t b0, uint32_t b1, CUtensorMapSwizzle sw)
{
    cuuint64_t dims[2] = {d0, d1};
    cuuint64_t strides[1] = {stride1};
    cuuint32_t box[2] = {b0, b1};
    cuuint32_t es[2] = {1, 1};
    enc(m, CU_TENSOR_MAP_DATA_TYPE_BFLOAT16, 2, p, dims, strides, box, es,
        CU_TENSOR_MAP_INTERLEAVE_NONE, sw, CU_TENSOR_MAP_L2_PROMOTION_L2_128B,
        CU_TENSOR_MAP_FLOAT_OOB_FILL_NONE);
}

extern "C" void kernel_launch(void* const* d_in, const int* in_sizes, int n_in,
                              void* d_out, int out_size)
{
    const float* x     = (const float*)d_in[0];
    const float* W_qkv = (const float*)d_in[1];
    const float* b_qkv = (const float*)d_in[2];
    const float* W_out = (const float*)d_in[3];
    const float* b_out = (const float*)d_in[4];
    const int*   maskp = (const int*)d_in[5];
    float* outp = (float*)d_out;

    __nv_bfloat16 *qkvhi, *qkvlo, *xhi, *xlo, *w1hi, *w1lo, *w2hi, *w2lo, *ohi, *olo;
    cudaGetSymbolAddress((void**)&qkvhi, g_qkvhi);
    cudaGetSymbolAddress((void**)&qkvlo, g_qkvlo);
    cudaGetSymbolAddress((void**)&xhi,  g_xhi);
    cudaGetSymbolAddress((void**)&xlo,  g_xlo);
    cudaGetSymbolAddress((void**)&w1hi, g_w1hi);
    cudaGetSymbolAddress((void**)&w1lo, g_w1lo);
    cudaGetSymbolAddress((void**)&w2hi, g_w2hi);
    cudaGetSymbolAddress((void**)&w2lo, g_w2lo);
    cudaGetSymbolAddress((void**)&ohi,  g_ohi);
    cudaGetSymbolAddress((void**)&olo,  g_olo);

    PFN_tmEncode enc = nullptr;
    {
        void* fn = nullptr;
        cudaDriverEntryPointQueryResult qr;
        cudaGetDriverEntryPoint("cuTensorMapEncodeTiled", &fn,
                                cudaEnableDefault, &qr);
        enc = (PFN_tmEncode)fn;
    }

    CUtensorMap tXhi, tXlo, tW1hi, tW1lo, tOhi, tOlo, tW2hi, tW2lo, tQhi, tQlo;
    make2d(enc, &tXhi,  xhi,  DMODEL, MTOT,   DMODEL * 2, 32, 128, CU_TENSOR_MAP_SWIZZLE_64B);
    make2d(enc, &tXlo,  xlo,  DMODEL, MTOT,   DMODEL * 2, 32, 128, CU_TENSOR_MAP_SWIZZLE_64B);
    make2d(enc, &tW1hi, w1hi, DMODEL, TD,     DMODEL * 2, 32, 128, CU_TENSOR_MAP_SWIZZLE_64B);
    make2d(enc, &tW1lo, w1lo, DMODEL, TD,     DMODEL * 2, 32, 128, CU_TENSOR_MAP_SWIZZLE_64B);
    make2d(enc, &tOhi,  ohi,  DMODEL, MTOT,   DMODEL * 2, 32, 128, CU_TENSOR_MAP_SWIZZLE_64B);
    make2d(enc, &tOlo,  olo,  DMODEL, MTOT,   DMODEL * 2, 32, 128, CU_TENSOR_MAP_SWIZZLE_64B);
    make2d(enc, &tW2hi, w2hi, DMODEL, DMODEL, DMODEL * 2, 32, 128, CU_TENSOR_MAP_SWIZZLE_64B);
    make2d(enc, &tW2lo, w2lo, DMODEL, DMODEL, DMODEL * 2, 32, 128, CU_TENSOR_MAP_SWIZZLE_64B);
    make2d(enc, &tQhi,  qkvhi, TD, MTOT, TD * 2, 64, 64, CU_TENSOR_MAP_SWIZZLE_128B);
    make2d(enc, &tQlo,  qkvlo, TD, MTOT, TD * 2, 64, 64, CU_TENSOR_MAP_SWIZZLE_128B);

    cudaFuncSetAttribute(gemm_bf16x3,
                         cudaFuncAttributeMaxDynamicSharedMemorySize, GSMEM);
    cudaFuncSetAttribute(gemm_bf16x3,
                         cudaFuncAttributePreferredSharedMemoryCarveout, 100);
    cudaFuncSetAttribute(attn_flash_hmma,
                         cudaFuncAttributeMaxDynamicSharedMemorySize, ASMEM);
    cudaFuncSetAttribute(attn_flash_hmma,
                         cudaFuncAttributePreferredSharedMemoryCarveout, 100);

    // 1) fused prep
    prep_kernel<<<PREP_BLKS, 256>>>(x, xhi, xlo, W_qkv, w1hi, w1lo,
                                    W_out, w2hi, w2lo);

    // 2) QKV projection (persistent)
    {
        int nbx = TD / 128, ntiles = nbx * (MTOT / 128);
        gemm_bf16x3<<<NSM_X2, 256, GSMEM>>>(tXhi, tXlo, tW1hi, tW1lo, b_qkv,
                                            nullptr, qkvhi, qkvlo, 1,
                                            MTOT, TD, DMODEL, ntiles, nbx);
    }
    // 3) flash attention (persistent, balanced schedule)
    attn_flash_hmma<<<NSM_X2, 256, ASMEM>>>(tQhi, tQlo, ohi, olo, maskp);

    // 4) output projection (persistent)
    {
        int nbx = DMODEL / 128, ntiles = nbx * (MTOT / 128);
        gemm_bf16x3<<<NSM_X2, 256, GSMEM>>>(tOhi, tOlo, tW2hi, tW2lo, b_out,
                                            outp, nullptr, nullptr, 0,
                                            MTOT, DMODEL, DMODEL, ntiles, nbx);
    }
}